// round 1
// baseline (speedup 1.0000x reference)
#include <cuda_runtime.h>

// LorentzAvgPool2d: x[32,128,128,64] fp32 NHWC -> out[32,64,64,64]
// 2x2/stride-2 avg pool, then Lorentz centroid normalization:
//   inner = -a0^2 + sum_{c>0} a_c^2
//   out   = a * rsqrt(max(|inner|, 1e-8))      (k=1)

static constexpr int B = 32;
static constexpr int H = 128;
static constexpr int W = 128;
static constexpr int C = 64;
static constexpr int OH = H / 2;
static constexpr int OW = W / 2;
static constexpr int NPIX = B * OH * OW;          // 131072 output pixels
static constexpr float EPS = 1e-8f;

// One 16-lane group per output pixel; each lane owns 4 channels (float4).
__global__ __launch_bounds__(256) void lorentz_avgpool_kernel(
    const float* __restrict__ x, float* __restrict__ out)
{
    const int tid   = blockIdx.x * blockDim.x + threadIdx.x;
    const int group = tid >> 4;            // global pixel index
    const int lane  = tid & 15;            // channel group within pixel
    if (group >= NPIX) return;

    const int ow = group % OW;
    const int oh = (group / OW) % OH;
    const int b  = group / (OW * OH);

    const int ih = oh * 2;
    const int iw = ow * 2;

    // base element offset of input pixel (b, ih, iw), channel 0
    const long base = ((long)(b * H + ih) * W + iw) * C;
    const float4* p00 = reinterpret_cast<const float4*>(x + base) + lane;
    const float4* p01 = reinterpret_cast<const float4*>(x + base + C) + lane;
    const float4* p10 = reinterpret_cast<const float4*>(x + base + (long)W * C) + lane;
    const float4* p11 = reinterpret_cast<const float4*>(x + base + (long)W * C + C) + lane;

    const float4 a = __ldg(p00);
    const float4 bb = __ldg(p01);
    const float4 c = __ldg(p10);
    const float4 d = __ldg(p11);

    float4 avg;
    avg.x = (a.x + bb.x + c.x + d.x) * 0.25f;
    avg.y = (a.y + bb.y + c.y + d.y) * 0.25f;
    avg.z = (a.z + bb.z + c.z + d.z) * 0.25f;
    avg.w = (a.w + bb.w + c.w + d.w) * 0.25f;

    // partial Lorentz inner product; lane 0's first channel is the time coord
    float s = avg.x * avg.x;
    if (lane == 0) s = -s;
    s += avg.y * avg.y + avg.z * avg.z + avg.w * avg.w;

    // reduce across the 16-lane group
    s += __shfl_xor_sync(0xFFFFFFFFu, s, 1);
    s += __shfl_xor_sync(0xFFFFFFFFu, s, 2);
    s += __shfl_xor_sync(0xFFFFFFFFu, s, 4);
    s += __shfl_xor_sync(0xFFFFFFFFu, s, 8);

    const float inv = rsqrtf(fmaxf(fabsf(s), EPS));

    float4 r;
    r.x = avg.x * inv;
    r.y = avg.y * inv;
    r.z = avg.z * inv;
    r.w = avg.w * inv;

    const long obase = (long)group * C;
    reinterpret_cast<float4*>(out + obase)[lane] = r;
}

extern "C" void kernel_launch(void* const* d_in, const int* in_sizes, int n_in,
                              void* d_out, int out_size)
{
    const float* x = (const float*)d_in[0];
    float* out = (float*)d_out;

    const int threads = 256;
    const int pix_per_block = threads / 16;               // 16
    const int blocks = (NPIX + pix_per_block - 1) / pix_per_block;  // 8192
    lorentz_avgpool_kernel<<<blocks, threads>>>(x, out);
}

// round 2
// speedup vs baseline: 1.0045x; 1.0045x over previous
#include <cuda_runtime.h>

// LorentzAvgPool2d: x[32,128,128,64] fp32 NHWC -> out[32,64,64,64]
// 2x2/stride-2 avg pool, then Lorentz centroid normalization:
//   inner = -a0^2 + sum_{c>0} a_c^2
//   out   = a * rsqrt(max(|inner|, 1e-8))      (k=1)
//
// R2: each 16-lane group produces TWO ow-adjacent output pixels
//     -> 8 independent LDG.128 per thread (2KB contiguous per group),
//     streaming cache hints (no reuse).

static constexpr int B = 32;
static constexpr int H = 128;
static constexpr int W = 128;
static constexpr int C = 64;
static constexpr int OH = H / 2;
static constexpr int OW = W / 2;
static constexpr int NPIX = B * OH * OW;          // 131072 output pixels
static constexpr int NGRP = NPIX / 2;             // 65536 groups (2 pixels each)
static constexpr float EPS = 1e-8f;

__device__ __forceinline__ float4 ld_cs4(const float4* p) { return __ldcs(p); }

__global__ __launch_bounds__(256) void lorentz_avgpool_kernel(
    const float* __restrict__ x, float* __restrict__ out)
{
    const int tid   = blockIdx.x * blockDim.x + threadIdx.x;
    const int group = tid >> 4;            // global group index (2 output pixels)
    const int lane  = tid & 15;            // channel group within pixel
    if (group >= NGRP) return;

    // group -> (b, oh, ow2) with ow = ow2*2
    const int ow2 = group & (OW / 2 - 1);               // 0..31
    const int oh  = (group >> 5) & (OH - 1);            // 0..63
    const int b   = group >> 11;                        // 0..31

    const int ih = oh * 2;
    const int iw = ow2 * 4;                             // input col of first window

    // base element offset of input pixel (b, ih, iw), channel 0
    const long base0 = ((long)(b * H + ih) * W + iw) * C;   // row ih
    const long base1 = base0 + (long)W * C;                 // row ih+1

    const float4* r0 = reinterpret_cast<const float4*>(x + base0) + lane;
    const float4* r1 = reinterpret_cast<const float4*>(x + base1) + lane;
    const int PC = C / 4;   // float4s per pixel = 16

    // 8 independent loads, front-batched
    const float4 a00 = ld_cs4(r0 + 0 * PC);
    const float4 a01 = ld_cs4(r0 + 1 * PC);
    const float4 a02 = ld_cs4(r0 + 2 * PC);
    const float4 a03 = ld_cs4(r0 + 3 * PC);
    const float4 a10 = ld_cs4(r1 + 0 * PC);
    const float4 a11 = ld_cs4(r1 + 1 * PC);
    const float4 a12 = ld_cs4(r1 + 2 * PC);
    const float4 a13 = ld_cs4(r1 + 3 * PC);

    // window 0: cols iw, iw+1 ; window 1: cols iw+2, iw+3
    float4 avg0, avg1;
    avg0.x = (a00.x + a01.x + a10.x + a11.x) * 0.25f;
    avg0.y = (a00.y + a01.y + a10.y + a11.y) * 0.25f;
    avg0.z = (a00.z + a01.z + a10.z + a11.z) * 0.25f;
    avg0.w = (a00.w + a01.w + a10.w + a11.w) * 0.25f;
    avg1.x = (a02.x + a03.x + a12.x + a13.x) * 0.25f;
    avg1.y = (a02.y + a03.y + a12.y + a13.y) * 0.25f;
    avg1.z = (a02.z + a03.z + a12.z + a13.z) * 0.25f;
    avg1.w = (a02.w + a03.w + a12.w + a13.w) * 0.25f;

    // partial Lorentz inner products; lane 0's first channel is the time coord
    float s0 = avg0.x * avg0.x;
    float s1 = avg1.x * avg1.x;
    if (lane == 0) { s0 = -s0; s1 = -s1; }
    s0 += avg0.y * avg0.y + avg0.z * avg0.z + avg0.w * avg0.w;
    s1 += avg1.y * avg1.y + avg1.z * avg1.z + avg1.w * avg1.w;

    // reduce across the 16-lane group (both pixels in parallel)
    #pragma unroll
    for (int m = 1; m < 16; m <<= 1) {
        s0 += __shfl_xor_sync(0xFFFFFFFFu, s0, m);
        s1 += __shfl_xor_sync(0xFFFFFFFFu, s1, m);
    }

    const float inv0 = rsqrtf(fmaxf(fabsf(s0), EPS));
    const float inv1 = rsqrtf(fmaxf(fabsf(s1), EPS));

    float4 o0, o1;
    o0.x = avg0.x * inv0; o0.y = avg0.y * inv0;
    o0.z = avg0.z * inv0; o0.w = avg0.w * inv0;
    o1.x = avg1.x * inv1; o1.y = avg1.y * inv1;
    o1.z = avg1.z * inv1; o1.w = avg1.w * inv1;

    // output pixels group*2 and group*2+1 -> 512B contiguous per group
    float4* op = reinterpret_cast<float4*>(out + (long)group * 2 * C) + lane;
    __stcs(op, o0);
    __stcs(op + PC, o1);
}

extern "C" void kernel_launch(void* const* d_in, const int* in_sizes, int n_in,
                              void* d_out, int out_size)
{
    const float* x = (const float*)d_in[0];
    float* out = (float*)d_out;

    const int threads = 256;
    const int grp_per_block = threads / 16;               // 16
    const int blocks = (NGRP + grp_per_block - 1) / grp_per_block;  // 4096
    lorentz_avgpool_kernel<<<blocks, threads>>>(x, out);
}